// round 7
// baseline (speedup 1.0000x reference)
#include <cuda_runtime.h>

// ---------------------------------------------------------------------------
// Problem constants + smem layout
// ---------------------------------------------------------------------------
namespace {
constexpr int   N    = 4096;
constexpr int   DIM  = 100;
constexpr int   HID  = 110;
constexpr int   T    = 50;
constexpr float DT   = 0.02f;
constexpr float EPS  = 1e-6f;
constexpr int   GRID = 128;       // co-resident blocks (1 per SM)
constexpr int   NT   = 512;       // threads per block
constexpr int   WS   = 112;       // weight tile col stride (16B aligned quads)

// smem offsets in floats
constexpr int OF_W1 = 0;                    // [100][112]
constexpr int OF_W2 = OF_W1 + DIM * WS;     // [110][112]
constexpr int OF_W3 = OF_W2 + HID * WS;     // [110][112]
constexpr int OF_X  = OF_W3 + HID * WS;     // [100][34]  x state  [k][r]
constexpr int OF_A  = OF_X + DIM * 34;      // [110][34]  h1 / h3 tile
constexpr int OF_B  = OF_A + HID * 34;      // [110][34]  h2 tile / staged dw
constexpr int OF_D  = OF_B + HID * 34;      // [110][64]  duplicated gemm input
constexpr int OF_Y  = OF_D + HID * 64;      // [32]       y state
constexpr int OF_AF = OF_Y + 32;            // [112] affine a
constexpr int OF_BF = OF_AF + 112;          // [112] affine c
constexpr int SMF   = OF_BF + 112;          // 54016 floats = 216064 bytes
}

// ---------------------------------------------------------------------------
// Global state
// ---------------------------------------------------------------------------
__device__ float g_dwT[(size_t)T * N * DIM];   // dw transposed [T][N][DIM]
__device__ float g_s0[2 * DIM];
__device__ float g_s1[2 * HID];
__device__ float g_s2[2 * HID];
__device__ float g_s3[2 * DIM];
__device__ float g_acc[2];
// tree barrier: 8 group counters (one 128B line each) + root + generation
__device__ unsigned g_grp[8 * 32];
__device__ unsigned g_root;
__device__ unsigned g_gen;

__device__ __forceinline__ void affine_coef(float sum, float sumsq, float w,
                                            float b, float& a, float& c) {
    float mean = sum * (1.0f / N);
    float var  = fmaf(-mean, mean, sumsq * (1.0f / N)) + EPS;
    float r    = rsqrtf(var);
    r = r * (1.5f - 0.5f * var * r * r);   // Newton refine
    a = w * r;
    c = fmaf(-mean, a, b);
}

// grid barrier: 8x16 tree, monotonic generations, acquire/release + fences
__device__ __forceinline__ void gbar(unsigned& target) {
    __syncthreads();
    if (threadIdx.x == 0) {
        const unsigned b = target;
        __threadfence();
        const int g = blockIdx.x & 7;                       // 16 blocks/group
        unsigned old = atomicAdd(&g_grp[g * 32], 1u);
        if (old == b * 16u - 1u) {                          // last in group
            unsigned r = atomicAdd(&g_root, 1u);
            if (r == b * 8u - 1u) {                         // last group
                asm volatile("st.release.gpu.global.u32 [%0], %1;"
                             :: "l"(&g_gen), "r"(b) : "memory");
            }
        }
        unsigned cur;
        do {
            asm volatile("ld.acquire.gpu.global.u32 %0, [%1];"
                         : "=r"(cur) : "l"(&g_gen) : "memory");
        } while (cur < b);
        __threadfence();
    }
    __syncthreads();
    ++target;
}

#define FMA2(acc, a, b) \
    asm("fma.rn.f32x2 %0, %1, %2, %0;" : "+l"(acc) : "l"(a), "l"(b))

// ---------------------------------------------------------------------------
// Transpose dw [N*DIM, T] -> [T, N*DIM]; block (0,0) also resets global state
// ---------------------------------------------------------------------------
__global__ void transpose_dw(const float* __restrict__ in) {
    __shared__ float s[32][33];
    const int tx = threadIdx.x, ty = threadIdx.y;
    const int tid = ty * 32 + tx;
    if (blockIdx.x == 0 && blockIdx.y == 0) {
        for (int k = tid; k < 2 * DIM; k += 256) { g_s0[k] = 0.f; g_s3[k] = 0.f; }
        for (int k = tid; k < 2 * HID; k += 256) { g_s1[k] = 0.f; g_s2[k] = 0.f; }
        if (tid < 8) g_grp[tid * 32] = 0u;
        if (tid == 0) { g_acc[0] = 0.f; g_acc[1] = 0.f; g_root = 0u; g_gen = 0u; }
    }
    const int ij0 = blockIdx.x * 32;
    const int t0  = blockIdx.y * 32;
#pragma unroll
    for (int i = 0; i < 32; i += 8) {
        int t = t0 + tx;
        int ij = ij0 + ty + i;
        if (t < T) s[ty + i][tx] = in[(size_t)ij * T + t];
    }
    __syncthreads();
#pragma unroll
    for (int i = 0; i < 32; i += 8) {
        int t = t0 + ty + i;
        int ij = ij0 + tx;
        if (t < T) g_dwT[(size_t)t * (N * DIM) + ij] = s[tx][ty + i];
    }
}

// ---------------------------------------------------------------------------
// BN affine (+relu) on [K x 32] tile -> duplicated layout dup[k*64 + 2r] = {v,v}
// ---------------------------------------------------------------------------
template <int K, bool RELU>
__device__ __forceinline__ void prep(const float* __restrict__ gStat,
                                     const float* __restrict__ bnw,
                                     const float* __restrict__ bnb,
                                     const float* __restrict__ src,
                                     float* __restrict__ dup,
                                     float* __restrict__ sAf,
                                     float* __restrict__ sBf) {
    const int tid = threadIdx.x;
    for (int k = tid; k < K; k += NT) {
        float a, c;
        affine_coef(__ldcg(&gStat[k]), __ldcg(&gStat[K + k]), bnw[k], bnb[k], a, c);
        sAf[k] = a; sBf[k] = c;
    }
    __syncthreads();
    for (int idx = tid; idx < K * 32; idx += NT) {
        int k = idx >> 5, r = idx & 31;
        float v = fmaf(src[k * 34 + r], sAf[k], sBf[k]);
        if (RELU) v = fmaxf(v, 0.f);
        *reinterpret_cast<float2*>(dup + (k << 6) + 2 * r) = make_float2(v, v);
    }
    __syncthreads();
}

// ---------------------------------------------------------------------------
// GEMM: sO[c*34+r] = sum_k dup[k][r] * sW[k*WS+c]  (+ bias[c]); FFMA2 mainloop
// ---------------------------------------------------------------------------
template <int K, int C, bool BIAS>
__device__ __forceinline__ void gemm(const float* __restrict__ sD,
                                     const float* __restrict__ sW,
                                     float* __restrict__ sO,
                                     const float* __restrict__ bias) {
    const int warp = threadIdx.x >> 5, lane = threadIdx.x & 31;
    const int cb = (warp >> 1) * 16;
    if (cb >= C) return;
    const int r0 = ((warp & 1) << 4) + ((lane & 7) << 1);
    const int c0 = cb + ((lane >> 3) << 2);
    unsigned long long a00 = 0ull, a01 = 0ull, a10 = 0ull, a11 = 0ull;
#pragma unroll 2
    for (int k = 0; k < K; ++k) {
        const float* dk = sD + (k << 6) + 2 * r0;
        unsigned long long x0 = *reinterpret_cast<const unsigned long long*>(dk);
        unsigned long long x1 = *reinterpret_cast<const unsigned long long*>(dk + 2);
        ulonglong2 w = *reinterpret_cast<const ulonglong2*>(sW + k * WS + c0);
        FMA2(a00, w.x, x0);
        FMA2(a01, w.y, x0);
        FMA2(a10, w.x, x1);
        FMA2(a11, w.y, x1);
    }
    float v00, v01, v02, v03, v10, v11, v12, v13;
    asm("mov.b64 {%0,%1}, %2;" : "=f"(v00), "=f"(v01) : "l"(a00));
    asm("mov.b64 {%0,%1}, %2;" : "=f"(v02), "=f"(v03) : "l"(a01));
    asm("mov.b64 {%0,%1}, %2;" : "=f"(v10), "=f"(v11) : "l"(a10));
    asm("mov.b64 {%0,%1}, %2;" : "=f"(v12), "=f"(v13) : "l"(a11));
    float c0v[4] = {v00, v01, v02, v03};
    float c1v[4] = {v10, v11, v12, v13};
#pragma unroll
    for (int c = 0; c < 4; ++c) {
        const int col = c0 + c;
        if (col < C) {
            float b = BIAS ? __ldg(&bias[col]) : 0.f;
            *reinterpret_cast<float2*>(&sO[col * 34 + r0]) =
                make_float2(c0v[c] + b, c1v[c] + b);
        }
    }
}

// per-column sum / sumsq over [C x 32] tile -> global RED
template <int C>
__device__ __forceinline__ void statp(const float* __restrict__ sO,
                                      float* __restrict__ gStat) {
    const int tid = threadIdx.x;
    if (tid < C) {
        float s = 0.f, q = 0.f;
#pragma unroll
        for (int r = 0; r < 32; r += 2) {
            float2 v = *reinterpret_cast<const float2*>(&sO[tid * 34 + r]);
            s += v.x + v.y;
            q = fmaf(v.x, v.x, fmaf(v.y, v.y, q));
        }
        atomicAdd(&gStat[tid], s);
        atomicAdd(&gStat[C + tid], q);
    }
}

// spread-zero: each block clears its slice of a stat buffer (1 thread, <=2 sts)
template <int SZ>
__device__ __forceinline__ void zero_spread(float* __restrict__ gStat) {
    if (threadIdx.x == 0)
        for (int k = blockIdx.x; k < SZ; k += GRID) __stcg(&gStat[k], 0.f);
}

// ---------------------------------------------------------------------------
// The persistent kernel: all 50 steps in one launch
// ---------------------------------------------------------------------------
__global__ void __launch_bounds__(NT, 1) persistK(
    const float* __restrict__ zinit, const float* __restrict__ yinit,
    const float* __restrict__ bn0w, const float* __restrict__ bn0b,
    const float* __restrict__ w1,   const float* __restrict__ bn1w,
    const float* __restrict__ bn1b, const float* __restrict__ w2,
    const float* __restrict__ bn2w, const float* __restrict__ bn2b,
    const float* __restrict__ w3,   const float* __restrict__ b3,
    const float* __restrict__ bn3w, const float* __restrict__ bn3b,
    float* __restrict__ out_loss, float* __restrict__ out_y,
    float* __restrict__ out_ye,   float* __restrict__ out_xs,
    float* __restrict__ out_us)
{
    extern __shared__ float sm[];
    float* sW1 = sm + OF_W1;
    float* sW2 = sm + OF_W2;
    float* sW3 = sm + OF_W3;
    float* sX  = sm + OF_X;
    float* sTa = sm + OF_A;
    float* sTb = sm + OF_B;       // h2 tile; also holds staged dw[t+1] tile
    float* sD  = sm + OF_D;
    float* sy  = sm + OF_Y;
    float* sAf = sm + OF_AF;
    float* sBf = sm + OF_BF;

    const int tid   = threadIdx.x;
    const int warp  = tid >> 5, lane = tid & 31;
    const int rbase = blockIdx.x * 32;
    unsigned target = 1;

    // zero weight pads + x state
    for (int i = tid; i < OF_X; i += NT) sm[i] = 0.f;
    for (int i = tid; i < DIM * 34; i += NT) sX[i] = 0.f;
    __syncthreads();
    // load weights once: sW[k*WS + c] = W[c*K + k]
    for (int idx = tid; idx < HID * DIM; idx += NT) {   // W1 [110,100]
        int c = idx / DIM, k = idx - c * DIM;
        sW1[k * WS + c] = w1[idx];
    }
    for (int idx = tid; idx < HID * HID; idx += NT) {   // W2 [110,110]
        int c = idx / HID, k = idx - c * HID;
        sW2[k * WS + c] = w2[idx];
    }
    for (int idx = tid; idx < DIM * HID; idx += NT) {   // W3 [100,110]
        int c = idx / HID, k = idx - c * HID;
        sW3[k * WS + c] = w3[idx];
    }
    const float y0 = yinit[0];

    for (int t = 0; t < T; ++t) {
        const bool first = (t == 0), last = (t == T - 1);

        // ---------------- phase A ----------------
        if (!first) {
            for (int k = tid; k < DIM; k += NT) {
                float a, c;
                affine_coef(__ldcg(&g_s3[k]), __ldcg(&g_s3[DIM + k]),
                            bn3w[k], bn3b[k], a, c);
                sAf[k] = a * 1e-4f;   // /DIM (subnet) * /DIM (z update)
                sBf[k] = c * 1e-4f;
            }
        }
        if (!last) zero_spread<2 * HID>(g_s2);
        __syncthreads();

        const float* dwt = g_dwT + ((size_t)t * N + rbase) * DIM;
        float* xsO = out_xs + ((size_t)t * N + rbase) * DIM;

#pragma unroll
        for (int it = 0; it < 2; ++it) {
            const int r = it * 16 + warp;
            const int i = rbase + r;
            float sz = 0.f, zdw = 0.f, xx = 0.f;
            float xo[4], dwv[4];
#pragma unroll
            for (int c2 = 0; c2 < 4; ++c2) {
                int j = lane + 32 * c2;
                xo[c2] = 0.f; dwv[c2] = 0.f;
                if (j < DIM) {
                    float z = first ? zinit[j]
                                    : fmaf(sTa[j * 34 + r], sAf[j], sBf[j]);
                    dwv[c2] = first ? dwt[(size_t)r * DIM + j]
                                    : sTb[r * DIM + j];     // staged by prev GEMM3
                    xo[c2]  = sX[j * 34 + r];
                    sz  += z;
                    zdw += z * dwv[c2];
                    xx  += xo[c2] * xo[c2];
                }
            }
#pragma unroll
            for (int o = 16; o; o >>= 1) {
                sz  += __shfl_xor_sync(~0u, sz, o);
                zdw += __shfl_xor_sync(~0u, zdw, o);
                xx  += __shfl_xor_sync(~0u, xx, o);
            }
            const float u = fminf(fmaxf(-sz, -1.f), 1.f);
            float yv = first ? y0 : sy[r];
            yv = yv - DT * 0.5f * (xx + u * u) + DT * sz * u + zdw;
            if (lane == 0) {
                out_us[(size_t)t * N + i] = u;
                if (last) {
                    out_y[i] = yv;
                    float ye = 0.5f * xx;
                    out_ye[i] = ye;
                    float d = yv - ye, ad = fabsf(d);
                    atomicAdd(&g_acc[0], (ad < 1.f) ? 0.5f * d * d : ad - 0.5f);
                    atomicAdd(&g_acc[1], ye);
                } else {
                    sy[r] = yv;
                }
            }
#pragma unroll
            for (int c2 = 0; c2 < 4; ++c2) {
                int j = lane + 32 * c2;
                if (j < DIM) {
                    xsO[(size_t)r * DIM + j] = xo[c2];
                    if (!last)
                        sX[j * 34 + r] = fmaf(xo[c2], 1.f - DT,
                                              fmaf(u, DT, dwv[c2]));
                }
            }
        }
        __syncthreads();

        if (last) {
            gbar(target);
            if (blockIdx.x == 0 && tid == 0) {
                float m1 = __ldcg(&g_acc[0]) * (1.0f / N);
                float m2 = __ldcg(&g_acc[1]) * (1.0f / N);
                out_loss[0] = 100.0f * (m1 + m2 * m2);
            }
            break;
        }

        statp<DIM>(sX, g_s0);
        gbar(target);

        // ---------------- GEMM1: h1 = bn0(x) @ W1^T ----------------
        zero_spread<2 * DIM>(g_s3);
        prep<DIM, false>(g_s0, bn0w, bn0b, sX, sD, sAf, sBf);
        gemm<DIM, HID, false>(sD, sW1, sTa, nullptr);
        __syncthreads();
        statp<HID>(sTa, g_s1);
        gbar(target);

        // ---------------- GEMM2: h2 = relu(bn1(h1)) @ W2^T ----------------
        zero_spread<2 * DIM>(g_s0);
        prep<HID, true>(g_s1, bn1w, bn1b, sTa, sD, sAf, sBf);
        gemm<HID, HID, false>(sD, sW2, sTb, nullptr);
        __syncthreads();
        statp<HID>(sTb, g_s2);
        gbar(target);

        // ---------------- GEMM3: h3 = relu(bn2(h2)) @ W3^T + b3 --------
        // warps 14-15 are idle in this gemm (cb >= 100): they stage dw[t+1]
        zero_spread<2 * HID>(g_s1);
        prep<HID, true>(g_s2, bn2w, bn2b, sTb, sD, sAf, sBf);
        if (warp < 14) {
            gemm<HID, DIM, true>(sD, sW3, sTa, b3);
        } else {
            // linear copy of 32x100 dw tile for step t+1 into sTb
            const float* src = g_dwT + ((size_t)(t + 1) * N + rbase) * DIM;
            for (int q = tid - 448; q < 800; q += 64) {
                float4 v = *reinterpret_cast<const float4*>(src + q * 4);
                *reinterpret_cast<float4*>(sTb + q * 4) = v;
            }
        }
        __syncthreads();
        statp<DIM>(sTa, g_s3);
        gbar(target);
    }
}

// ---------------------------------------------------------------------------
// Launcher
// ---------------------------------------------------------------------------
extern "C" void kernel_launch(void* const* d_in, const int* in_sizes, int n_in,
                              void* d_out, int out_size) {
    const float* dw    = (const float*)d_in[0];
    const float* yinit = (const float*)d_in[1];
    const float* zinit = (const float*)d_in[2];
    const float* bn0w  = (const float*)d_in[3];
    const float* bn0b  = (const float*)d_in[4];
    const float* w1    = (const float*)d_in[5];
    const float* bn1w  = (const float*)d_in[6];
    const float* bn1b  = (const float*)d_in[7];
    const float* w2    = (const float*)d_in[8];
    const float* bn2w  = (const float*)d_in[9];
    const float* bn2b  = (const float*)d_in[10];
    const float* w3    = (const float*)d_in[11];
    const float* b3    = (const float*)d_in[12];
    const float* bn3w  = (const float*)d_in[13];
    const float* bn3b  = (const float*)d_in[14];

    float* out    = (float*)d_out;
    float* out_y  = out + 1;
    float* out_ye = out + 1 + N;
    float* out_xs = out + 1 + 2 * N;
    float* out_us = out_xs + (size_t)T * N * DIM;

    static int attr_done = 0;
    if (!attr_done) {
        cudaFuncSetAttribute(persistK,
                             cudaFuncAttributeMaxDynamicSharedMemorySize,
                             SMF * (int)sizeof(float));
        attr_done = 1;
    }

    transpose_dw<<<dim3(N * DIM / 32, 2), dim3(32, 8)>>>(dw);
    persistK<<<GRID, NT, SMF * sizeof(float)>>>(
        zinit, yinit, bn0w, bn0b, w1, bn1w, bn1b, w2, bn2w, bn2b,
        w3, b3, bn3w, bn3b, out, out_y, out_ye, out_xs, out_us);
}

// round 9
// speedup vs baseline: 1.1166x; 1.1166x over previous
#include <cuda_runtime.h>

// ---------------------------------------------------------------------------
// Problem constants + smem layout
// ---------------------------------------------------------------------------
namespace {
constexpr int   N    = 4096;
constexpr int   DIM  = 100;
constexpr int   HID  = 110;
constexpr int   T    = 50;
constexpr float DT   = 0.02f;
constexpr float EPS  = 1e-6f;
constexpr int   GRID = 128;       // co-resident blocks (1 per SM)
constexpr int   NT   = 512;       // threads per block
constexpr int   WS   = 112;       // weight tile col stride (16B aligned quads)

// smem offsets in floats
constexpr int OF_W1 = 0;                    // [100][112]
constexpr int OF_W2 = OF_W1 + DIM * WS;     // [110][112]
constexpr int OF_W3 = OF_W2 + HID * WS;     // [110][112]
constexpr int OF_X  = OF_W3 + HID * WS;     // [100][34]  x state  [k][r]
constexpr int OF_A  = OF_X + DIM * 34;      // [110][34]  h1 / h3 tile
constexpr int OF_B  = OF_A + HID * 34;      // [110][34]  h2 tile
constexpr int OF_D  = OF_B + HID * 34;      // [110][64]  duplicated gemm input
constexpr int OF_Y  = OF_D + HID * 64;      // [32]       y state
constexpr int OF_AF = OF_Y + 32;            // [112] affine a
constexpr int OF_BF = OF_AF + 112;          // [112] affine c
constexpr int SMF   = OF_BF + 112;          // 54016 floats = 216064 bytes
}

// ---------------------------------------------------------------------------
// Global state
// ---------------------------------------------------------------------------
__device__ float g_dwT[(size_t)T * N * DIM];   // dw transposed [T][N][DIM]
__device__ float g_s0[2 * DIM];
__device__ float g_s1[2 * HID];
__device__ float g_s2[2 * HID];
__device__ float g_s3[2 * DIM];
__device__ float g_acc[2];
__device__ unsigned g_cnt;
__device__ volatile unsigned g_gen;

__device__ __forceinline__ void affine_coef(float sum, float sumsq, float w,
                                            float b, float& a, float& c) {
    float mean = sum * (1.0f / N);
    float var  = fmaf(-mean, mean, sumsq * (1.0f / N)) + EPS;
    float r    = rsqrtf(var);
    r = r * (1.5f - 0.5f * var * r * r);   // Newton refine
    a = w * r;
    c = fmaf(-mean, a, b);
}

// flat grid barrier (R6-proven): all GRID blocks resident by construction
__device__ __forceinline__ void gbar(unsigned& target) {
    __syncthreads();
    if (threadIdx.x == 0) {
        __threadfence();
        if (atomicAdd(&g_cnt, 1u) == (unsigned)(GRID - 1)) {
            atomicExch(&g_cnt, 0u);
            __threadfence();
            g_gen = target;
        } else {
            while (g_gen < target) { __nanosleep(32); }
        }
        __threadfence();
    }
    __syncthreads();
    ++target;
}

#define FMA2(acc, a, b) \
    asm("fma.rn.f32x2 %0, %1, %2, %0;" : "+l"(acc) : "l"(a), "l"(b))

// ---------------------------------------------------------------------------
__global__ void initK() {
    int tid = threadIdx.x;
    for (int k = tid; k < 2 * DIM; k += 256) { g_s0[k] = 0.f; g_s3[k] = 0.f; }
    for (int k = tid; k < 2 * HID; k += 256) { g_s1[k] = 0.f; g_s2[k] = 0.f; }
    if (tid == 0) { g_acc[0] = 0.f; g_acc[1] = 0.f; g_cnt = 0u; g_gen = 0u; }
}

// Transpose dw [N*DIM, T] -> [T, N*DIM]
__global__ void transpose_dw(const float* __restrict__ in) {
    __shared__ float s[32][33];
    const int ij0 = blockIdx.x * 32;
    const int t0  = blockIdx.y * 32;
    const int tx  = threadIdx.x, ty = threadIdx.y;
#pragma unroll
    for (int i = 0; i < 32; i += 8) {
        int t = t0 + tx;
        int ij = ij0 + ty + i;
        if (t < T) s[ty + i][tx] = in[(size_t)ij * T + t];
    }
    __syncthreads();
#pragma unroll
    for (int i = 0; i < 32; i += 8) {
        int t = t0 + ty + i;
        int ij = ij0 + tx;
        if (t < T) g_dwT[(size_t)t * (N * DIM) + ij] = s[tx][ty + i];
    }
}

// ---------------------------------------------------------------------------
// BN affine (+relu) on [K x 32] tile -> interleaved duplicated layout:
//   per k (64-float row), 16-byte chunk q holds dup pairs of rows:
//   chunks 0..7  = rows {0,1},{4,5},...,{28,29}
//   chunks 8..15 = rows {2,3},{6,7},...,{30,31}
// so gemm's LDS.128 per lane-group hits 8 distinct consecutive chunks (1 wf).
// ---------------------------------------------------------------------------
template <int K, bool RELU>
__device__ __forceinline__ void prep(const float* __restrict__ gStat,
                                     const float* __restrict__ bnw,
                                     const float* __restrict__ bnb,
                                     const float* __restrict__ src,
                                     float* __restrict__ dup,
                                     float* __restrict__ sAf,
                                     float* __restrict__ sBf) {
    const int tid = threadIdx.x;
    for (int k = tid; k < K; k += NT) {
        float a, c;
        affine_coef(__ldcg(&gStat[k]), __ldcg(&gStat[K + k]), bnw[k], bnb[k], a, c);
        sAf[k] = a; sBf[k] = c;
    }
    __syncthreads();
    for (int idx = tid; idx < K * 32; idx += NT) {
        int k = idx >> 5, r = idx & 31;
        float v = fmaf(src[k * 34 + r], sAf[k], sBf[k]);
        if (RELU) v = fmaxf(v, 0.f);
        int off = ((r & 2) ? 32 : 0) + (r >> 2) * 4 + (r & 1) * 2;
        *reinterpret_cast<float2*>(dup + (k << 6) + off) = make_float2(v, v);
    }
    __syncthreads();
}

// ---------------------------------------------------------------------------
// GEMM: sO[c*34+r] = sum_k dup[k][r] * sW[k*WS+c]  (+ bias[c])
// 7 active warps (warp 0..6), lane tile = 4 rows x 4 cols.
// warp w covers cols 16w..16w+15 (pads >= C are zero); rows 0..31.
// Per warp per k: 2x LDS.128 (x dup, conflict-free) + 1x LDS.128 (w)
// + 8 FFMA2  -> 3 smem wavefronts/warp/k, FMA-bound overall.
// Epilogue uses float2 stores ONLY (col*34 is not 16B aligned for odd col).
// ---------------------------------------------------------------------------
template <int K, int C, bool BIAS>
__device__ __forceinline__ void gemm(const float* __restrict__ sD,
                                     const float* __restrict__ sW,
                                     float* __restrict__ sO,
                                     const float* __restrict__ bias) {
    const int warp = threadIdx.x >> 5, lane = threadIdx.x & 31;
    if (warp >= 7) return;
    const int g  = lane & 7;                         // row group: rows 4g..4g+3
    const int c0 = warp * 16 + ((lane >> 3) << 2);   // 4 cols, c0+3 <= 111
    const int r0 = 4 * g;

    unsigned long long acc[4][2];
#pragma unroll
    for (int r = 0; r < 4; ++r) { acc[r][0] = 0ull; acc[r][1] = 0ull; }

    const float* pD = sD + 4 * g;            // chunk g
    const float* pW = sW + c0;
#pragma unroll 2
    for (int k = 0; k < K; ++k) {
        // rows {4g,4g+1} dup'd then {4g+2,4g+3} dup'd
        ulonglong2 xa = *reinterpret_cast<const ulonglong2*>(pD);
        ulonglong2 xb = *reinterpret_cast<const ulonglong2*>(pD + 32);
        ulonglong2 w  = *reinterpret_cast<const ulonglong2*>(pW);
        FMA2(acc[0][0], w.x, xa.x);
        FMA2(acc[0][1], w.y, xa.x);
        FMA2(acc[1][0], w.x, xa.y);
        FMA2(acc[1][1], w.y, xa.y);
        FMA2(acc[2][0], w.x, xb.x);
        FMA2(acc[2][1], w.y, xb.x);
        FMA2(acc[3][0], w.x, xb.y);
        FMA2(acc[3][1], w.y, xb.y);
        pD += 64;
        pW += WS;
    }

    // unpack: v[r][c], c = 0..3 relative to c0
    float v[4][4];
#pragma unroll
    for (int r = 0; r < 4; ++r) {
        asm("mov.b64 {%0,%1}, %2;" : "=f"(v[r][0]), "=f"(v[r][1]) : "l"(acc[r][0]));
        asm("mov.b64 {%0,%1}, %2;" : "=f"(v[r][2]), "=f"(v[r][3]) : "l"(acc[r][1]));
    }
#pragma unroll
    for (int c = 0; c < 4; ++c) {
        const int col = c0 + c;
        if (col < C) {
            float b = BIAS ? __ldg(&bias[col]) : 0.f;
            float* dst = &sO[col * 34 + r0];           // even offset: 8B aligned
            *reinterpret_cast<float2*>(dst)     = make_float2(v[0][c] + b, v[1][c] + b);
            *reinterpret_cast<float2*>(dst + 2) = make_float2(v[2][c] + b, v[3][c] + b);
        }
    }
}

// per-column sum / sumsq over [C x 32] tile -> global RED
template <int C>
__device__ __forceinline__ void statp(const float* __restrict__ sO,
                                      float* __restrict__ gStat) {
    const int tid = threadIdx.x;
    if (tid < C) {
        float s = 0.f, q = 0.f;
#pragma unroll
        for (int r = 0; r < 32; r += 2) {
            float2 v = *reinterpret_cast<const float2*>(&sO[tid * 34 + r]);
            s += v.x + v.y;
            q = fmaf(v.x, v.x, fmaf(v.y, v.y, q));
        }
        atomicAdd(&gStat[tid], s);
        atomicAdd(&gStat[C + tid], q);
    }
}

// ---------------------------------------------------------------------------
// The persistent kernel: all 50 steps in one launch
// ---------------------------------------------------------------------------
__global__ void __launch_bounds__(NT, 1) persistK(
    const float* __restrict__ zinit, const float* __restrict__ yinit,
    const float* __restrict__ bn0w, const float* __restrict__ bn0b,
    const float* __restrict__ w1,   const float* __restrict__ bn1w,
    const float* __restrict__ bn1b, const float* __restrict__ w2,
    const float* __restrict__ bn2w, const float* __restrict__ bn2b,
    const float* __restrict__ w3,   const float* __restrict__ b3,
    const float* __restrict__ bn3w, const float* __restrict__ bn3b,
    float* __restrict__ out_loss, float* __restrict__ out_y,
    float* __restrict__ out_ye,   float* __restrict__ out_xs,
    float* __restrict__ out_us)
{
    extern __shared__ float sm[];
    float* sW1 = sm + OF_W1;
    float* sW2 = sm + OF_W2;
    float* sW3 = sm + OF_W3;
    float* sX  = sm + OF_X;
    float* sTa = sm + OF_A;
    float* sTb = sm + OF_B;
    float* sD  = sm + OF_D;
    float* sy  = sm + OF_Y;
    float* sAf = sm + OF_AF;
    float* sBf = sm + OF_BF;

    const int tid   = threadIdx.x;
    const int warp  = tid >> 5, lane = tid & 31;
    const int rbase = blockIdx.x * 32;
    unsigned target = 1;

    // zero weight region (pads) + x state
    for (int i = tid; i < OF_X; i += NT) sm[i] = 0.f;
    for (int i = tid; i < DIM * 34; i += NT) sX[i] = 0.f;
    __syncthreads();
    // load weights once: sW[k*WS + c] = W[c*K + k]
    for (int idx = tid; idx < HID * DIM; idx += NT) {   // W1 [110,100]
        int c = idx / DIM, k = idx - c * DIM;
        sW1[k * WS + c] = w1[idx];
    }
    for (int idx = tid; idx < HID * HID; idx += NT) {   // W2 [110,110]
        int c = idx / HID, k = idx - c * HID;
        sW2[k * WS + c] = w2[idx];
    }
    for (int idx = tid; idx < DIM * HID; idx += NT) {   // W3 [100,110]
        int c = idx / HID, k = idx - c * HID;
        sW3[k * WS + c] = w3[idx];
    }
    const float y0 = yinit[0];

    for (int t = 0; t < T; ++t) {
        const bool first = (t == 0), last = (t == T - 1);

        // ---------------- phase A ----------------
        if (!first) {
            for (int k = tid; k < DIM; k += NT) {
                float a, c;
                affine_coef(__ldcg(&g_s3[k]), __ldcg(&g_s3[DIM + k]),
                            bn3w[k], bn3b[k], a, c);
                sAf[k] = a * 1e-4f;   // /DIM (subnet) * /DIM (z update)
                sBf[k] = c * 1e-4f;
            }
        }
        if (!last && blockIdx.x == 0)
            for (int k = tid; k < 2 * HID; k += NT) __stcg(&g_s2[k], 0.f);
        __syncthreads();

        const float* dwt = g_dwT + ((size_t)t * N + rbase) * DIM;
        float* xsO = out_xs + ((size_t)t * N + rbase) * DIM;

#pragma unroll
        for (int it = 0; it < 2; ++it) {
            const int r = it * 16 + warp;
            const int i = rbase + r;
            float sz = 0.f, zdw = 0.f, xx = 0.f;
            float xo[4], dwv[4];
#pragma unroll
            for (int c2 = 0; c2 < 4; ++c2) {
                int j = lane + 32 * c2;
                xo[c2] = 0.f; dwv[c2] = 0.f;
                if (j < DIM) {
                    float z = first ? zinit[j]
                                    : fmaf(sTa[j * 34 + r], sAf[j], sBf[j]);
                    dwv[c2] = dwt[(size_t)r * DIM + j];
                    xo[c2]  = sX[j * 34 + r];
                    sz  += z;
                    zdw += z * dwv[c2];
                    xx  += xo[c2] * xo[c2];
                }
            }
#pragma unroll
            for (int o = 16; o; o >>= 1) {
                sz  += __shfl_xor_sync(~0u, sz, o);
                zdw += __shfl_xor_sync(~0u, zdw, o);
                xx  += __shfl_xor_sync(~0u, xx, o);
            }
            const float u = fminf(fmaxf(-sz, -1.f), 1.f);
            float yv = first ? y0 : sy[r];
            yv = yv - DT * 0.5f * (xx + u * u) + DT * sz * u + zdw;
            if (lane == 0) {
                out_us[(size_t)t * N + i] = u;
                if (last) {
                    out_y[i] = yv;
                    float ye = 0.5f * xx;
                    out_ye[i] = ye;
                    float d = yv - ye, ad = fabsf(d);
                    atomicAdd(&g_acc[0], (ad < 1.f) ? 0.5f * d * d : ad - 0.5f);
                    atomicAdd(&g_acc[1], ye);
                } else {
                    sy[r] = yv;
                }
            }
#pragma unroll
            for (int c2 = 0; c2 < 4; ++c2) {
                int j = lane + 32 * c2;
                if (j < DIM) {
                    xsO[(size_t)r * DIM + j] = xo[c2];
                    if (!last)
                        sX[j * 34 + r] = fmaf(xo[c2], 1.f - DT,
                                              fmaf(u, DT, dwv[c2]));
                }
            }
        }
        __syncthreads();

        if (last) {
            gbar(target);
            if (blockIdx.x == 0 && tid == 0) {
                float m1 = __ldcg(&g_acc[0]) * (1.0f / N);
                float m2 = __ldcg(&g_acc[1]) * (1.0f / N);
                out_loss[0] = 100.0f * (m1 + m2 * m2);
            }
            break;
        }

        statp<DIM>(sX, g_s0);
        gbar(target);

        // ---------------- GEMM1: h1 = bn0(x) @ W1^T ----------------
        if (blockIdx.x == 0)
            for (int k = tid; k < 2 * DIM; k += NT) __stcg(&g_s3[k], 0.f);
        prep<DIM, false>(g_s0, bn0w, bn0b, sX, sD, sAf, sBf);
        gemm<DIM, HID, false>(sD, sW1, sTa, nullptr);
        __syncthreads();
        statp<HID>(sTa, g_s1);
        gbar(target);

        // ---------------- GEMM2: h2 = relu(bn1(h1)) @ W2^T ----------------
        if (blockIdx.x == 0)
            for (int k = tid; k < 2 * DIM; k += NT) __stcg(&g_s0[k], 0.f);
        prep<HID, true>(g_s1, bn1w, bn1b, sTa, sD, sAf, sBf);
        gemm<HID, HID, false>(sD, sW2, sTb, nullptr);
        __syncthreads();
        statp<HID>(sTb, g_s2);
        gbar(target);

        // ---------------- GEMM3: h3 = relu(bn2(h2)) @ W3^T + b3 --------
        if (blockIdx.x == 0)
            for (int k = tid; k < 2 * HID; k += NT) __stcg(&g_s1[k], 0.f);
        prep<HID, true>(g_s2, bn2w, bn2b, sTb, sD, sAf, sBf);
        gemm<HID, DIM, true>(sD, sW3, sTa, b3);
        __syncthreads();
        statp<DIM>(sTa, g_s3);
        gbar(target);
    }
}

// ---------------------------------------------------------------------------
// Launcher
// ---------------------------------------------------------------------------
extern "C" void kernel_launch(void* const* d_in, const int* in_sizes, int n_in,
                              void* d_out, int out_size) {
    const float* dw    = (const float*)d_in[0];
    const float* yinit = (const float*)d_in[1];
    const float* zinit = (const float*)d_in[2];
    const float* bn0w  = (const float*)d_in[3];
    const float* bn0b  = (const float*)d_in[4];
    const float* w1    = (const float*)d_in[5];
    const float* bn1w  = (const float*)d_in[6];
    const float* bn1b  = (const float*)d_in[7];
    const float* w2    = (const float*)d_in[8];
    const float* bn2w  = (const float*)d_in[9];
    const float* bn2b  = (const float*)d_in[10];
    const float* w3    = (const float*)d_in[11];
    const float* b3    = (const float*)d_in[12];
    const float* bn3w  = (const float*)d_in[13];
    const float* bn3b  = (const float*)d_in[14];

    float* out    = (float*)d_out;
    float* out_y  = out + 1;
    float* out_ye = out + 1 + N;
    float* out_xs = out + 1 + 2 * N;
    float* out_us = out_xs + (size_t)T * N * DIM;

    static int attr_done = 0;
    if (!attr_done) {
        cudaFuncSetAttribute(persistK,
                             cudaFuncAttributeMaxDynamicSharedMemorySize,
                             SMF * (int)sizeof(float));
        attr_done = 1;
    }

    initK<<<1, 256>>>();
    transpose_dw<<<dim3(N * DIM / 32, 2), dim3(32, 8)>>>(dw);
    persistK<<<GRID, NT, SMF * sizeof(float)>>>(
        zinit, yinit, bn0w, bn0b, w1, bn1w, bn1b, w2, bn2w, bn2b,
        w3, b3, bn3w, bn3b, out, out_y, out_ye, out_xs, out_us);
}